// round 16
// baseline (speedup 1.0000x reference)
#include <cuda_runtime.h>
#include <cuda_bf16.h>

#define M_NODES 10000
#define T_STEPS 40
#define KNN     16
#define FSEM    32
#define EPSV    1e-8f

// One 64B record per (tt,j) — ONE 128B line holds everything the k-phase needs:
//   a = (pref.xyz, 1/(2 sig^2+eps))
//   b = q_rel = qnorm(q_live[t]) * conj(qnorm(q_ref[tt]))
//   e = p_live - qrot(q_rel, pref)      [mu_k = qrot(q_rel, xw) + e]
//   pad = zero (MUST be finite: SEL-excluded lanes still touch it)
struct __align__(64) NRec { float4 a, b, e, pad; };
__device__ NRec g_R[T_STEPS * M_NODES];   // 25.6 MB, L2-resident

struct Quat { float w, x, y, z; };

__device__ __forceinline__ Quat qnormalize(Quat q) {
    float n2 = q.w * q.w + q.x * q.x + q.y * q.y + q.z * q.z;
    float inv = rsqrtf(fmaxf(n2, 1e-24f));   // matches reference clip(norm,1e-12)
    Quat r; r.w = q.w * inv; r.x = q.x * inv; r.y = q.y * inv; r.z = q.z * inv;
    return r;
}

__device__ __forceinline__ Quat qload(float4 v) {
    Quat q; q.w = v.x; q.x = v.y; q.y = v.z; q.z = v.w; return q;
}

__device__ __forceinline__ Quat qmul(Quat a, Quat b) {
    Quat r;
    r.w = a.w * b.w - a.x * b.x - a.y * b.y - a.z * b.z;
    r.x = a.w * b.x + a.x * b.w + a.y * b.z - a.z * b.y;
    r.y = a.w * b.y - a.x * b.z + a.y * b.w + a.z * b.x;
    r.z = a.w * b.z + a.x * b.y - a.y * b.x + a.z * b.w;
    return r;
}

// RAW q2R (no internal normalize): for q ~ 0 yields ~I (reference degenerate path).
__device__ __forceinline__ void q2R(Quat q, float R[3][3]) {
    float w = q.w, x = q.x, y = q.y, z = q.z;
    R[0][0] = 1.f - 2.f * (y * y + z * z);
    R[0][1] = 2.f * (x * y - w * z);
    R[0][2] = 2.f * (x * z + w * y);
    R[1][0] = 2.f * (x * y + w * z);
    R[1][1] = 1.f - 2.f * (x * x + z * z);
    R[1][2] = 2.f * (y * z - w * x);
    R[2][0] = 2.f * (x * z - w * y);
    R[2][1] = 2.f * (y * z + w * x);
    R[2][2] = 1.f - 2.f * (x * x + y * y);
}

__device__ __forceinline__ void mat3mul(const float A[3][3], const float B[3][3], float C[3][3]) {
    #pragma unroll
    for (int i = 0; i < 3; i++)
        #pragma unroll
        for (int j = 0; j < 3; j++)
            C[i][j] = A[i][0] * B[0][j] + A[i][1] * B[1][j] + A[i][2] * B[2][j];
}

__device__ __forceinline__ float3 qrot(Quat q, float3 v) {
    float tx = 2.f * (q.y * v.z - q.z * v.y);
    float ty = 2.f * (q.z * v.x - q.x * v.z);
    float tz = 2.f * (q.x * v.y - q.y * v.x);
    float3 r;
    r.x = v.x + q.w * tx + (q.y * tz - q.z * ty);
    r.y = v.y + q.w * ty + (q.z * tx - q.x * tz);
    r.z = v.z + q.w * tz + (q.x * ty - q.y * tx);
    return r;
}

__device__ __forceinline__ float sigmoidf(float x) {
    return 1.f / (1.f + __expf(-x));
}

__device__ __forceinline__ float qw_sum(float v) {
    v += __shfl_xor_sync(0xffffffffu, v, 4);
    v += __shfl_xor_sync(0xffffffffu, v, 2);
    v += __shfl_xor_sync(0xffffffffu, v, 1);
    return v;
}

// ---- precompute kernel: one thread per (tt, j) ----
__global__ void __launch_bounds__(256)
dyn_scf_pre_kernel(
    const float*  __restrict__ node_xyz,
    const float4* __restrict__ node_quat,
    const float*  __restrict__ node_sigma,
    const int*    __restrict__ t_ptr)
{
    int idx = blockIdx.x * blockDim.x + threadIdx.x;
    if (idx >= T_STEPS * M_NODES) return;
    int j = idx % M_NODES;
    int t = __ldg(t_ptr);
    long tMj = (long)t * M_NODES + j;

    Quat qr = qnormalize(qload(__ldg(&node_quat[idx])));
    Quat ql = qnormalize(qload(__ldg(&node_quat[tMj])));
    // q_rel = ql * conj(qr)
    Quat q;
    q.w =  ql.w * qr.w + ql.x * qr.x + ql.y * qr.y + ql.z * qr.z;
    q.x = -ql.w * qr.x + ql.x * qr.w - ql.y * qr.z + ql.z * qr.y;
    q.y = -ql.w * qr.y + ql.x * qr.z + ql.y * qr.w - ql.z * qr.x;
    q.z = -ql.w * qr.z - ql.x * qr.y + ql.y * qr.x + ql.z * qr.w;

    float sig = __ldg(&node_sigma[j]);
    float3 pr = { __ldg(&node_xyz[3L * idx]),
                  __ldg(&node_xyz[3L * idx + 1]),
                  __ldg(&node_xyz[3L * idx + 2]) };
    float3 pl = { __ldg(&node_xyz[3L * tMj]),
                  __ldg(&node_xyz[3L * tMj + 1]),
                  __ldg(&node_xyz[3L * tMj + 2]) };
    float3 rp = qrot(q, pr);

    g_R[idx].a = make_float4(pr.x, pr.y, pr.z, 1.f / (2.f * sig * sig + EPSV));
    g_R[idx].b = make_float4(q.w, q.x, q.y, q.z);
    g_R[idx].e = make_float4(pl.x - rp.x, pl.y - rp.y, pl.z - rp.z, 0.f);
    g_R[idx].pad = make_float4(0.f, 0.f, 0.f, 0.f);   // finite: SEL'd lanes read it
}

// ---- FUSED kernel: main skinning blocks + elementwise blocks ----
__global__ void __launch_bounds__(256, 5)
dyn_scf_fused_kernel(
    const float*  __restrict__ gs_xyz,     // (N,3)
    const float4* __restrict__ gs_rot,     // (N,4)
    const float4* __restrict__ node_quat,  // (T,M,4)
    const float4* __restrict__ node_sem4,  // (M,32) as M x 8 float4
    const int*    __restrict__ attach,     // (N,)
    const int*    __restrict__ ref_time,   // (N,)
    const int2*   __restrict__ topo2,      // (M,K) as M x 8 int2
    const float4* __restrict__ gs_scal4,   // (N,3) as 3N/4 float4
    const float4* __restrict__ gs_op4,     // (N,)  as N/4 float4
    const float*  __restrict__ feat_dc,    // (N,3)
    const float*  __restrict__ feat_rest,  // (N,9)
    float*        __restrict__ out,
    int N, int main_blocks)
{
    if (blockIdx.x >= main_blocks) {
        // ================= elem path =================
        long e = (long)(blockIdx.x - main_blocks) * blockDim.x + threadIdx.x;
        const long ns4 = 3L * N / 4;
        const long no4 = (long)N / 4;
        float4* o_s4   = (float4*)(out + 12L * N);
        float4* o_o4   = (float4*)(out + 15L * N);
        float4* o_sph4 = (float4*)(out + 16L * N);

        if (e < ns4) {
            float4 v = __ldg(&gs_scal4[e]);
            v.x = 0.1f * sigmoidf(v.x); v.y = 0.1f * sigmoidf(v.y);
            v.z = 0.1f * sigmoidf(v.z); v.w = 0.1f * sigmoidf(v.w);
            o_s4[e] = v;
        } else if (e < ns4 + no4) {
            long i = e - ns4;
            float4 v = __ldg(&gs_op4[i]);
            v.x = sigmoidf(v.x); v.y = sigmoidf(v.y);
            v.z = sigmoidf(v.z); v.w = sigmoidf(v.w);
            o_o4[i] = v;
        } else if (e < ns4 + no4 + 3L * N) {
            long s4 = e - ns4 - no4;
            int n = (int)(s4 / 3);
            int r = (int)(s4 - 3L * n);
            float4 v;
            const float* dc = feat_dc + 3 * n;
            const float* fr = feat_rest + 9 * n;
            if (r == 0) {
                v.x = __ldg(&dc[0]); v.y = __ldg(&dc[1]); v.z = __ldg(&dc[2]); v.w = __ldg(&fr[0]);
            } else if (r == 1) {
                v.x = __ldg(&fr[1]); v.y = __ldg(&fr[2]); v.z = __ldg(&fr[3]); v.w = __ldg(&fr[4]);
            } else {
                v.x = __ldg(&fr[5]); v.y = __ldg(&fr[6]); v.z = __ldg(&fr[7]); v.w = __ldg(&fr[8]);
            }
            o_sph4[s4] = v;
        }
        return;
    }

    // ================= main skinning path =================
    const int lane = threadIdx.x & 31;
    const int kl   = lane & 7;
    const int grp  = (lane >> 3) & 3;
    const long warp_gid = (long)blockIdx.x * (blockDim.x >> 5) + (threadIdx.x >> 5);
    const int n = (int)(warp_gid * 4 + grp);
    if (n >= N) return;   // N % 32 == 0 -> warps never partial

    const int a  = __ldg(&attach[n]);
    const int rt = __ldg(&ref_time[n]);
    const long rtM = (long)rt * M_NODES;

    // lane kl owns topo pair kl: (j_{2kl}, j_{2kl+1})
    const int2 jj = __ldg(&topo2[a * (KNN / 2) + kl]);

    const int base8 = lane & 24;   // group base lane (absolute)
    const int s     = kl & 3;      // record slot this lane loads (0=a,1=b,2=e,3=pad)
    const int sub   = kl >> 2;     // which of the 2 records per instruction

    const float4* R4 = (const float4*)g_R;   // record j at float4 indices 4j..4j+3

    // ---- preamble ----
    float4 Aa = __ldg(&R4[(rtM + a) << 2]);          // slot a of attach record
    Quat qa = qnormalize(qload(__ldg(&node_quat[rtM + a])));
    Quat qg = qnormalize(qload(__ldg(&gs_rot[n])));

    float3 gx = { __ldg(&gs_xyz[3 * n]), __ldg(&gs_xyz[3 * n + 1]), __ldg(&gs_xyz[3 * n + 2]) };
    float3 xr = qrot(qa, gx);
    float3 xw = { xr.x + Aa.x, xr.y + Aa.y, xr.z + Aa.z };
    Quat qag = qmul(qa, qg);   // unit*unit -> unit; R_world = R(qag)

    // ---- k-phase: instruction m covers records 2m, 2m+1 per group; 4 lanes per
    // record load slots 0..3 of ONE 64B record -> 8 distinct lines per warp
    // instruction (vs 16 before), 64 total line-visits for ALL gather data.
    // Roles: s==0 computes w; s==1 accumulates w*qrot(q,xw); s==2 accumulates w*E.
    // mu = SUM w*qrot + SUM w*E  (sum split across roles; no result shuffles).
    float accS = 0.f;
    float3 accMu = { 0.f, 0.f, 0.f };
    Quat accQb = { 0.f, 0.f, 0.f, 0.f };
    float wsav[8];   // w of record 2m+sub, genuine on lane base8 + 4*sub

    #pragma unroll
    for (int c = 0; c < 2; c++) {
        float4 vA[4];
        #pragma unroll
        for (int mm = 0; mm < 4; mm++) {
            int m = 4 * c + mm;
            int jx = __shfl_sync(0xffffffffu, jj.x, base8 + m);
            int jy = __shfl_sync(0xffffffffu, jj.y, base8 + m);
            int j  = sub ? jy : jx;
            vA[mm] = __ldg(&R4[((rtM + j) << 2) + s]);
        }
        #pragma unroll
        for (int mm = 0; mm < 4; mm++) {
            int m = 4 * c + mm;
            float4 vm = vA[mm];
            // s==0 role (garbage on other lanes; SEL'd below, always finite)
            float dx = xw.x - vm.x, dy = xw.y - vm.y, dz = xw.z - vm.z;
            float w = __expf(-(dx * dx + dy * dy + dz * dz) * vm.w);
            wsav[m] = w;
            float wb = __shfl_sync(0xffffffffu, w, lane & ~3);  // from record's s0 lane
            // s==1 role
            Quat q; q.w = vm.x; q.x = vm.y; q.y = vm.z; q.z = vm.w;
            float3 mv = qrot(q, xw);
            // accumulate with SEL (never multiply garbage by 0: inf*0 = NaN)
            accS += (s == 0) ? w : 0.f;
            float wq = (s == 1) ? wb : 0.f;
            accQb.w += wq * q.w; accQb.x += wq * q.x;
            accQb.y += wq * q.y; accQb.z += wq * q.z;
            float wm2 = (s == 2) ? wb : 0.f;
            accMu.x += wq * mv.x + wm2 * vm.x;   // vm = E on s==2
            accMu.y += wq * mv.y + wm2 * vm.y;
            accMu.z += wq * mv.z + wm2 * vm.z;
        }
    }

    // ---- group reductions (role-partials sum to complete totals) ----
    float S   = qw_sum(accS);
    float mux = qw_sum(accMu.x);
    float muy = qw_sum(accMu.y);
    float muz = qw_sum(accMu.z);
    float qbw = qw_sum(accQb.w);
    float qbx = qw_sum(accQb.x);
    float qby = qw_sum(accQb.y);
    float qbz = qw_sum(accQb.z);

    float invS = 1.f / (S + EPSV);

    // ---- sem blend: record k -> w on lane base8+4*(k&1), register k>>1;
    //                 j on owner lane base8+(k>>1), component k&1 ----
    float4 sacc = make_float4(0.f, 0.f, 0.f, 0.f);
    #pragma unroll
    for (int k = 0; k < KNN; k++) {
        float wk = __shfl_sync(0xffffffffu, wsav[k >> 1], base8 + ((k & 1) << 2));
        int   jk = (k & 1) ? __shfl_sync(0xffffffffu, jj.y, base8 + (k >> 1))
                           : __shfl_sync(0xffffffffu, jj.x, base8 + (k >> 1));
        float4 vv = __ldg(&node_sem4[(long)jk * (FSEM / 4) + kl]);
        sacc.x += wk * vv.x; sacc.y += wk * vv.y;
        sacc.z += wk * vv.z; sacc.w += wk * vv.w;
    }

    // ---- frame epilogue: EXPLICIT Rb @ Rw (clip-safe; see R8 failure).
    // invS scaling BEFORE normalize is load-bearing (R2 failure).
    Quat qbn; qbn.w = qbw * invS; qbn.x = qbx * invS; qbn.y = qby * invS; qbn.z = qbz * invS;
    qbn = qnormalize(qbn);
    float Rb[3][3]; q2R(qbn, Rb);
    float Rw[3][3]; q2R(qag, Rw);
    float Fr[3][3]; mat3mul(Rb, Rw, Fr);

    // ---- outputs ----
    float*  o_mu  = out;
    float*  o_fr  = out + 3L  * N;
    float4* o_sem = (float4*)(out + 28L * N);

    float muv = (kl == 0) ? mux : ((kl == 1) ? muy : muz);
    if (kl < 3) o_mu[3 * n + kl] = muv * invS;

    float frv = Fr[0][0];
    frv = (kl == 1) ? Fr[0][1] : frv;
    frv = (kl == 2) ? Fr[0][2] : frv;
    frv = (kl == 3) ? Fr[1][0] : frv;
    frv = (kl == 4) ? Fr[1][1] : frv;
    frv = (kl == 5) ? Fr[1][2] : frv;
    frv = (kl == 6) ? Fr[2][0] : frv;
    frv = (kl == 7) ? Fr[2][1] : frv;
    o_fr[9 * n + kl] = frv;
    if (kl == 0) o_fr[9 * n + 8] = Fr[2][2];

    float4 sv; sv.x = sacc.x * invS; sv.y = sacc.y * invS;
    sv.z = sacc.z * invS; sv.w = sacc.w * invS;
    o_sem[(long)n * (FSEM / 4) + kl] = sv;
}

extern "C" void kernel_launch(void* const* d_in, const int* in_sizes, int n_in,
                              void* d_out, int out_size) {
    const float*  gs_xyz     = (const float*)d_in[0];
    const float4* gs_rot     = (const float4*)d_in[1];
    const float4* gs_scal4   = (const float4*)d_in[2];
    const float4* gs_op4     = (const float4*)d_in[3];
    const float*  feat_dc    = (const float*)d_in[4];
    const float*  feat_rest  = (const float*)d_in[5];
    const float*  node_xyz   = (const float*)d_in[6];
    const float4* node_quat  = (const float4*)d_in[7];
    const float*  node_sigma = (const float*)d_in[8];
    const float4* node_sem4  = (const float4*)d_in[9];
    const int*    attach     = (const int*)d_in[10];
    const int*    ref_time   = (const int*)d_in[11];
    const int2*   topo2      = (const int2*)d_in[12];
    const int*    t_ptr      = (const int*)d_in[13];

    int N = in_sizes[0] / 3;

    // 1) table precompute
    int pblocks = (T_STEPS * M_NODES + 255) / 256;
    dyn_scf_pre_kernel<<<pblocks, 256>>>(node_xyz, node_quat, node_sigma, t_ptr);

    // 2) fused main + elem
    int main_blocks = (N + 31) / 32;                       // 4 gaussians/warp, 8 warps/block
    long total4 = (3L * N) / 4 + (long)N / 4 + 3L * N;     // elem float4 units
    int elem_blocks = (int)((total4 + 255) / 256);
    dyn_scf_fused_kernel<<<main_blocks + elem_blocks, 256>>>(
        gs_xyz, gs_rot, node_quat, node_sem4,
        attach, ref_time, topo2,
        gs_scal4, gs_op4, feat_dc, feat_rest,
        (float*)d_out, N, main_blocks);
}

// round 17
// speedup vs baseline: 1.0639x; 1.0639x over previous
#include <cuda_runtime.h>
#include <cuda_bf16.h>

#define M_NODES 10000
#define T_STEPS 40
#define KNN     16
#define FSEM    32
#define EPSV    1e-8f

// Merged (tt,j)-indexed record: 32B aligned, a+b in one 32B sector of one line.
// a = (pref.xyz, 1/(2 sig^2+eps)); b = q_rel.
struct __align__(32) ABRec { float4 a, b; };
__device__ ABRec  g_AB[T_STEPS * M_NODES];   // 12.8 MB, L2-resident
__device__ float4 g_C[M_NODES];              // 160 KB -> L1-resident (p_live.xyz, 0)

struct Quat { float w, x, y, z; };

__device__ __forceinline__ Quat qnormalize(Quat q) {
    float n2 = q.w * q.w + q.x * q.x + q.y * q.y + q.z * q.z;
    float inv = rsqrtf(fmaxf(n2, 1e-24f));   // matches reference clip(norm,1e-12)
    Quat r; r.w = q.w * inv; r.x = q.x * inv; r.y = q.y * inv; r.z = q.z * inv;
    return r;
}

__device__ __forceinline__ Quat qload(float4 v) {
    Quat q; q.w = v.x; q.x = v.y; q.y = v.z; q.z = v.w; return q;
}

__device__ __forceinline__ Quat qmul(Quat a, Quat b) {
    Quat r;
    r.w = a.w * b.w - a.x * b.x - a.y * b.y - a.z * b.z;
    r.x = a.w * b.x + a.x * b.w + a.y * b.z - a.z * b.y;
    r.y = a.w * b.y - a.x * b.z + a.y * b.w + a.z * b.x;
    r.z = a.w * b.z + a.x * b.y - a.y * b.x + a.z * b.w;
    return r;
}

// RAW q2R (no internal normalize): for q ~ 0 yields ~I (reference degenerate path).
__device__ __forceinline__ void q2R(Quat q, float R[3][3]) {
    float w = q.w, x = q.x, y = q.y, z = q.z;
    R[0][0] = 1.f - 2.f * (y * y + z * z);
    R[0][1] = 2.f * (x * y - w * z);
    R[0][2] = 2.f * (x * z + w * y);
    R[1][0] = 2.f * (x * y + w * z);
    R[1][1] = 1.f - 2.f * (x * x + z * z);
    R[1][2] = 2.f * (y * z - w * x);
    R[2][0] = 2.f * (x * z - w * y);
    R[2][1] = 2.f * (y * z + w * x);
    R[2][2] = 1.f - 2.f * (x * x + y * y);
}

__device__ __forceinline__ void mat3mul(const float A[3][3], const float B[3][3], float C[3][3]) {
    #pragma unroll
    for (int i = 0; i < 3; i++)
        #pragma unroll
        for (int j = 0; j < 3; j++)
            C[i][j] = A[i][0] * B[0][j] + A[i][1] * B[1][j] + A[i][2] * B[2][j];
}

__device__ __forceinline__ float3 qrot(Quat q, float3 v) {
    float tx = 2.f * (q.y * v.z - q.z * v.y);
    float ty = 2.f * (q.z * v.x - q.x * v.z);
    float tz = 2.f * (q.x * v.y - q.y * v.x);
    float3 r;
    r.x = v.x + q.w * tx + (q.y * tz - q.z * ty);
    r.y = v.y + q.w * ty + (q.z * tx - q.x * tz);
    r.z = v.z + q.w * tz + (q.x * ty - q.y * tx);
    return r;
}

__device__ __forceinline__ float sigmoidf(float x) {
    return 1.f / (1.f + __expf(-x));
}

__device__ __forceinline__ float qw_sum(float v) {
    v += __shfl_xor_sync(0xffffffffu, v, 4);
    v += __shfl_xor_sync(0xffffffffu, v, 2);
    v += __shfl_xor_sync(0xffffffffu, v, 1);
    return v;
}

// ---- precompute kernel: one thread per (tt, j) ----
__global__ void __launch_bounds__(256)
dyn_scf_pre_kernel(
    const float*  __restrict__ node_xyz,
    const float4* __restrict__ node_quat,
    const float*  __restrict__ node_sigma,
    const int*    __restrict__ t_ptr)
{
    int idx = blockIdx.x * blockDim.x + threadIdx.x;
    if (idx >= T_STEPS * M_NODES) return;
    int j  = idx % M_NODES;
    int tt = idx / M_NODES;
    int t  = __ldg(t_ptr);
    long tMj = (long)t * M_NODES + j;

    Quat qr = qnormalize(qload(__ldg(&node_quat[idx])));
    Quat ql = qnormalize(qload(__ldg(&node_quat[tMj])));
    // q_rel = ql * conj(qr)
    float4 B;
    B.x =  ql.w * qr.w + ql.x * qr.x + ql.y * qr.y + ql.z * qr.z;
    B.y = -ql.w * qr.x + ql.x * qr.w - ql.y * qr.z + ql.z * qr.y;
    B.z = -ql.w * qr.y + ql.x * qr.z + ql.y * qr.w - ql.z * qr.x;
    B.w = -ql.w * qr.z - ql.x * qr.y + ql.y * qr.x + ql.z * qr.w;

    float sig = __ldg(&node_sigma[j]);
    float px = __ldg(&node_xyz[3L * idx]);
    float py = __ldg(&node_xyz[3L * idx + 1]);
    float pz = __ldg(&node_xyz[3L * idx + 2]);

    g_AB[idx].a = make_float4(px, py, pz, 1.f / (2.f * sig * sig + EPSV));
    g_AB[idx].b = B;
    if (tt == t) g_C[j] = make_float4(px, py, pz, 0.f);
}

// ---- FUSED kernel: main skinning blocks + elementwise blocks ----
// launch_bounds(256, 6): cap regs at 42 so 6 blocks (48 warps) fit per SM.
// R15 measured 48 regs / 5 blocks / occ 58% with issue 59% — occupancy is the
// remaining lever. The k-phase is chunked (2 records at a time) to cut peak
// float4 liveness 8 -> 4 so ptxas can reach 42 regs without spilling.
__global__ void __launch_bounds__(256, 6)
dyn_scf_fused_kernel(
    const float*  __restrict__ gs_xyz,     // (N,3)
    const float4* __restrict__ gs_rot,     // (N,4)
    const float4* __restrict__ node_quat,  // (T,M,4)
    const float4* __restrict__ node_sem4,  // (M,32) as M x 8 float4
    const int*    __restrict__ attach,     // (N,)
    const int*    __restrict__ ref_time,   // (N,)
    const int2*   __restrict__ topo2,      // (M,K) as M x 8 int2
    const float4* __restrict__ gs_scal4,   // (N,3) as 3N/4 float4
    const float4* __restrict__ gs_op4,     // (N,)  as N/4 float4
    const float*  __restrict__ feat_dc,    // (N,3)
    const float*  __restrict__ feat_rest,  // (N,9)
    float*        __restrict__ out,
    int N, int main_blocks)
{
    if (blockIdx.x >= main_blocks) {
        // ================= elem path =================
        long e = (long)(blockIdx.x - main_blocks) * blockDim.x + threadIdx.x;
        const long ns4 = 3L * N / 4;
        const long no4 = (long)N / 4;
        float4* o_s4   = (float4*)(out + 12L * N);
        float4* o_o4   = (float4*)(out + 15L * N);
        float4* o_sph4 = (float4*)(out + 16L * N);

        if (e < ns4) {
            float4 v = __ldg(&gs_scal4[e]);
            v.x = 0.1f * sigmoidf(v.x); v.y = 0.1f * sigmoidf(v.y);
            v.z = 0.1f * sigmoidf(v.z); v.w = 0.1f * sigmoidf(v.w);
            o_s4[e] = v;
        } else if (e < ns4 + no4) {
            long i = e - ns4;
            float4 v = __ldg(&gs_op4[i]);
            v.x = sigmoidf(v.x); v.y = sigmoidf(v.y);
            v.z = sigmoidf(v.z); v.w = sigmoidf(v.w);
            o_o4[i] = v;
        } else if (e < ns4 + no4 + 3L * N) {
            long s4 = e - ns4 - no4;
            int n = (int)(s4 / 3);
            int r = (int)(s4 - 3L * n);
            float4 v;
            const float* dc = feat_dc + 3 * n;
            const float* fr = feat_rest + 9 * n;
            if (r == 0) {
                v.x = __ldg(&dc[0]); v.y = __ldg(&dc[1]); v.z = __ldg(&dc[2]); v.w = __ldg(&fr[0]);
            } else if (r == 1) {
                v.x = __ldg(&fr[1]); v.y = __ldg(&fr[2]); v.z = __ldg(&fr[3]); v.w = __ldg(&fr[4]);
            } else {
                v.x = __ldg(&fr[5]); v.y = __ldg(&fr[6]); v.z = __ldg(&fr[7]); v.w = __ldg(&fr[8]);
            }
            o_sph4[s4] = v;
        }
        return;
    }

    // ================= main skinning path =================
    const int lane = threadIdx.x & 31;
    const int kl   = lane & 7;
    const int grp  = (lane >> 3) & 3;
    const long warp_gid = (long)blockIdx.x * (blockDim.x >> 5) + (threadIdx.x >> 5);
    const int n = (int)(warp_gid * 4 + grp);
    if (n >= N) return;   // N % 32 == 0 -> warps never partial

    const int a  = __ldg(&attach[n]);
    const int rt = __ldg(&ref_time[n]);
    const long rtM = (long)rt * M_NODES;

    // lane kl OWNS records 2kl (jj.x) and 2kl+1 (jj.y)
    const int2 jj = __ldg(&topo2[a * (KNN / 2) + kl]);

    const int base = lane & 24;        // group base lane (absolute)
    const int hf   = kl & 1;           // 0: load a-half, 1: load b-half
    const int comp = (kl >> 1) & 1;    // j component of my load-record
    const int quad = kl >> 2;          // owner offset within instruction

    const float4* AB4 = (const float4*)g_AB;   // record j at float4 indices 2j, 2j+1

    // ---- preamble ----
    float4 Aa = __ldg(&AB4[(rtM + a) * 2]);
    Quat qa = qnormalize(qload(__ldg(&node_quat[rtM + a])));
    Quat qg = qnormalize(qload(__ldg(&gs_rot[n])));

    float3 gx = { __ldg(&gs_xyz[3 * n]), __ldg(&gs_xyz[3 * n + 1]), __ldg(&gs_xyz[3 * n + 2]) };
    float3 xr = qrot(qa, gx);
    float3 xw = { xr.x + Aa.x, xr.y + Aa.y, xr.z + Aa.z };
    Quat qag = qmul(qa, qg);   // unit*unit -> unit; R_world = R(qag)

    // ---- pair-cooperative AB gather, CHUNKED 2 records at a time to cap peak
    // register liveness (4 live float4 instead of 8 -> fits the 42-reg budget).
    // Load instr m covers records 4m..4m+3; lane kl loads half hf of record
    // r = 4m + (kl>>1); owner lane of r = 2m + quad. Pairs share the record's
    // 128B line -> 16 distinct lines/instr instead of 32.
    float accS = 0.f;
    float3 accMu = { 0.f, 0.f, 0.f };
    Quat accQb = { 0.f, 0.f, 0.f, 0.f };
    float wsav[4];   // valid on even lanes: w of record 4m + kl/2

    #pragma unroll
    for (int c = 0; c < 2; c++) {
        // resolve j indices for the 2 records of this chunk
        int jmA, jmB;
        {
            int m0 = 2 * c, m1 = 2 * c + 1;
            int jx0 = __shfl_sync(0xffffffffu, jj.x, base + 2 * m0 + quad);
            int jy0 = __shfl_sync(0xffffffffu, jj.y, base + 2 * m0 + quad);
            int jx1 = __shfl_sync(0xffffffffu, jj.x, base + 2 * m1 + quad);
            int jy1 = __shfl_sync(0xffffffffu, jj.y, base + 2 * m1 + quad);
            jmA = comp ? jy0 : jx0;
            jmB = comp ? jy1 : jx1;
        }
        float4 vA = __ldg(&AB4[(rtM + jmA) * 2 + hf]);
        float4 vB = __ldg(&AB4[(rtM + jmB) * 2 + hf]);
        float4 CA = __ldg(&g_C[jmA]);   // L1-hot; pair shares the line
        float4 CB = __ldg(&g_C[jmB]);

        #pragma unroll
        for (int mm = 0; mm < 2; mm++) {
            int m = 2 * c + mm;
            float4 vm = mm ? vB : vA;
            float4 Cv = mm ? CB : CA;
            // even-lane role
            float3 d = { xw.x - vm.x, xw.y - vm.y, xw.z - vm.z };
            float dsq = d.x * d.x + d.y * d.y + d.z * d.z;
            float w = __expf(-dsq * vm.w);
            wsav[m] = w;
            // pair transfer (even -> odd)
            float dxr = __shfl_xor_sync(0xffffffffu, d.x, 1);
            float dyr = __shfl_xor_sync(0xffffffffu, d.y, 1);
            float dzr = __shfl_xor_sync(0xffffffffu, d.z, 1);
            float wr  = __shfl_xor_sync(0xffffffffu, w,   1);
            // odd-lane role
            Quat q; q.w = vm.x; q.x = vm.y; q.y = vm.z; q.z = vm.w;
            float3 dd = { dxr, dyr, dzr };
            float3 mv = qrot(q, dd);
            float wro = hf ? wr : 0.f;        // SEL: discards even-lane garbage wr
            float ws  = hf ? 0.f : w;         // SEL: discards odd-lane garbage w
            accS    += ws;
            accMu.x += wro * (mv.x + Cv.x);
            accMu.y += wro * (mv.y + Cv.y);
            accMu.z += wro * (mv.z + Cv.z);
            accQb.w += wro * q.w;
            accQb.x += wro * q.x;
            accQb.y += wro * q.y;
            accQb.z += wro * q.z;
        }
    }

    // ---- group reductions (partials per role; totals complete across 8 lanes) ----
    float S   = qw_sum(accS);
    float mux = qw_sum(accMu.x);
    float muy = qw_sum(accMu.y);
    float muz = qw_sum(accMu.z);
    float qbw = qw_sum(accQb.w);
    float qbx = qw_sum(accQb.x);
    float qby = qw_sum(accQb.y);
    float qbz = qw_sum(accQb.z);

    float invS = 1.f / (S + EPSV);

    // ---- sem blend: record k -> w at (register k>>2, even lane 2*(k&3));
    //                 j at (owner lane k>>1, component k&1) ----
    float4 sacc = make_float4(0.f, 0.f, 0.f, 0.f);
    #pragma unroll
    for (int k = 0; k < KNN; k++) {
        float wk = __shfl_sync(0xffffffffu, wsav[k >> 2], base + 2 * (k & 3));
        int   jk = (k & 1) ? __shfl_sync(0xffffffffu, jj.y, base + (k >> 1))
                           : __shfl_sync(0xffffffffu, jj.x, base + (k >> 1));
        float4 vv = __ldg(&node_sem4[(long)jk * (FSEM / 4) + kl]);
        sacc.x += wk * vv.x; sacc.y += wk * vv.y;
        sacc.z += wk * vv.z; sacc.w += wk * vv.w;
    }

    // ---- frame epilogue: EXPLICIT Rb @ Rw (clip-safe; see R8 failure).
    // invS scaling BEFORE normalize is load-bearing (R2 failure).
    Quat qbn; qbn.w = qbw * invS; qbn.x = qbx * invS; qbn.y = qby * invS; qbn.z = qbz * invS;
    qbn = qnormalize(qbn);
    float Rb[3][3]; q2R(qbn, Rb);
    float Rw[3][3]; q2R(qag, Rw);
    float Fr[3][3]; mat3mul(Rb, Rw, Fr);

    // ---- outputs ----
    float*  o_mu  = out;
    float*  o_fr  = out + 3L  * N;
    float4* o_sem = (float4*)(out + 28L * N);

    float muv = (kl == 0) ? mux : ((kl == 1) ? muy : muz);
    if (kl < 3) o_mu[3 * n + kl] = muv * invS;

    float frv = Fr[0][0];
    frv = (kl == 1) ? Fr[0][1] : frv;
    frv = (kl == 2) ? Fr[0][2] : frv;
    frv = (kl == 3) ? Fr[1][0] : frv;
    frv = (kl == 4) ? Fr[1][1] : frv;
    frv = (kl == 5) ? Fr[1][2] : frv;
    frv = (kl == 6) ? Fr[2][0] : frv;
    frv = (kl == 7) ? Fr[2][1] : frv;
    o_fr[9 * n + kl] = frv;
    if (kl == 0) o_fr[9 * n + 8] = Fr[2][2];

    float4 sv; sv.x = sacc.x * invS; sv.y = sacc.y * invS;
    sv.z = sacc.z * invS; sv.w = sacc.w * invS;
    o_sem[(long)n * (FSEM / 4) + kl] = sv;
}

extern "C" void kernel_launch(void* const* d_in, const int* in_sizes, int n_in,
                              void* d_out, int out_size) {
    const float*  gs_xyz     = (const float*)d_in[0];
    const float4* gs_rot     = (const float4*)d_in[1];
    const float4* gs_scal4   = (const float4*)d_in[2];
    const float4* gs_op4     = (const float4*)d_in[3];
    const float*  feat_dc    = (const float*)d_in[4];
    const float*  feat_rest  = (const float*)d_in[5];
    const float*  node_xyz   = (const float*)d_in[6];
    const float4* node_quat  = (const float4*)d_in[7];
    const float*  node_sigma = (const float*)d_in[8];
    const float4* node_sem4  = (const float4*)d_in[9];
    const int*    attach     = (const int*)d_in[10];
    const int*    ref_time   = (const int*)d_in[11];
    const int2*   topo2      = (const int2*)d_in[12];
    const int*    t_ptr      = (const int*)d_in[13];

    int N = in_sizes[0] / 3;

    // 1) table precompute
    int pblocks = (T_STEPS * M_NODES + 255) / 256;
    dyn_scf_pre_kernel<<<pblocks, 256>>>(node_xyz, node_quat, node_sigma, t_ptr);

    // 2) fused main + elem
    int main_blocks = (N + 31) / 32;                       // 4 gaussians/warp, 8 warps/block
    long total4 = (3L * N) / 4 + (long)N / 4 + 3L * N;     // elem float4 units
    int elem_blocks = (int)((total4 + 255) / 256);
    dyn_scf_fused_kernel<<<main_blocks + elem_blocks, 256>>>(
        gs_xyz, gs_rot, node_quat, node_sem4,
        attach, ref_time, topo2,
        gs_scal4, gs_op4, feat_dc, feat_rest,
        (float*)d_out, N, main_blocks);
}